// round 7
// baseline (speedup 1.0000x reference)
#include <cuda_runtime.h>

// SimplePhotonicRaytracer — GB300 sm_103a
//
// R6 measured: main kernel 96us, DRAM 39%, L1TEX 68% (top), occ 60%, regs=34.
// Diagnosis: (a) partial second wave — GRID sized for 8 CTAs/SM but 34 regs
// only allows 7; (b) unnecessary LDS traffic (sVar) through the busiest pipe.
// R7: __launch_bounds__(256,8) for a true single wave, and var computed in
// registers from the loaded float4 (FMA pipe was 93% idle).
//
// Output layout: d_out = [ feats (B*81*4 f32) | resp (B*81*3 f32) ]  (validated R6)

#define GCELLS 81
#define NDIG   10
#define NLUT   (GCELLS * NDIG)
#define BLOCK  256
#define GRID   1184   // 148 SMs * 8 CTAs — exactly one wave with launch_bounds(256,8)

__device__ float4 g_lut[NLUT];     // {r0, r1, r2, mean}

__global__ void build_lut_kernel(const float* __restrict__ ri,     // [81]
                                 const float* __restrict__ absorb, // [81*3]
                                 const float* __restrict__ tsp)    // [1]
{
    int e = blockIdx.x * blockDim.x + threadIdx.x;
    if (e >= NLUT) return;
    int c = e / NDIG;     // cell 0..80
    int d = e % NDIG;     // digit 0..9

    float n  = ri[c];
    float ts = *tsp;

    // heights = BASE_HEIGHT + thickness_scale * digit ; path = heights * n
    float height = 1e-4f + ts * (float)d;
    float path   = height * n;

    // Fresnel reflectance at normal incidence: R = ((1-n)/(1+n))^2
    float rr = (1.0f - n) / (1.0f + n);
    float tf = 1.0f - rr * rr;

    const float lam[3] = {6.5e-7f, 5.5e-7f, 4.5e-7f};
    float twopi_path = 6.283185307179586f * path;   // (2*pi*path)/lambda, ref op order

    float r[3];
#pragma unroll
    for (int w = 0; w < 3; ++w) {
        float alpha  = fabsf(absorb[c * 3 + w]);
        float trans  = expf(-alpha * path);                       // Beer's law
        float interf = 0.5f * (1.0f + cosf(twopi_path / lam[w])); // interference
        r[w] = tf * trans * interf;
    }

    float mean = (r[0] + r[1] + r[2]) * (1.0f / 3.0f);
    g_lut[e] = make_float4(r[0], r[1], r[2], mean);
}

__global__ void __launch_bounds__(BLOCK, 8)
photonic_main_kernel(const int* __restrict__ grid,   // [B*81]
                     float* __restrict__ feats,      // [B*81*4]
                     float* __restrict__ resp,       // [B*81*3]
                     int total)                      // B*81, divisible by 4
{
    __shared__ float4 sLut[NLUT];   // {r0,r1,r2,mean}
    __shared__ float  sMean[NLUT];  // scalar mean for neighbor probes (LDS.32, 4B stride)

    for (int k = threadIdx.x; k < NLUT; k += BLOCK) {
        float4 v = g_lut[k];
        sLut[k]  = v;
        sMean[k] = v.w;
    }
    __syncthreads();

    const int4* grid4  = reinterpret_cast<const int4*>(grid);
    float4*     feats4 = reinterpret_cast<float4*>(feats);
    float4*     resp4  = reinterpret_cast<float4*>(resp);

    int ngroups = total >> 2;
    int stride  = gridDim.x * blockDim.x;

    for (int v = blockIdx.x * blockDim.x + threadIdx.x; v < ngroups; v += stride) {
        int base = v << 2;

        // cell indices for the 4 elements (c0..c0+3 mod 81)
        int c0 = base % GCELLS;
        int cc[4];
#pragma unroll
        for (int k = 0; k < 4; ++k) {
            int c = c0 + k; if (c >= GCELLS) c -= GCELLS;
            cc[k] = c;
        }

        // ---- front-batch ALL global loads (MLP before any LDS) ----
        int4 g4 = grid4[v];
        int dig[4] = {g4.x, g4.y, g4.z, g4.w};

        int ndn[4];   // +9 (row) neighbor digits; guard row<8 keeps loads in-board
#pragma unroll
        for (int k = 0; k < 4; ++k)
            ndn[k] = (cc[k] < 72) ? __ldg(&grid[base + k + 9]) : 0;

        // +1 (col) neighbor for k=3; k<3 neighbors come from registers (dig[k+1])
        int nd3 = (cc[3] % 9 < 8) ? __ldg(&grid[base + 4]) : 0;

        // ---- LUT lookups + feature assembly (var in registers: FMA pipe idle) ----
        float rbuf[12];
        float4 fbuf[4];
#pragma unroll
        for (int k = 0; k < 4; ++k) {
            int c = cc[k];
            int j = c % 9;

            float4 rm = sLut[c * NDIG + dig[k]];

            // unbiased var (ddof=1, W=3): ((r0-m)^2+(r1-m)^2+(r2-m)^2)/2
            float d0 = rm.x - rm.w, d1 = rm.y - rm.w, d2 = rm.z - rm.w;
            float var = (d0 * d0 + d1 * d1 + d2 * d2) * 0.5f;

            // diff with append(last) => 0 at j==8 / row==8
            float gx = 0.0f, gy = 0.0f;
            if (j < 8) {
                int dr = (k < 3) ? dig[k + 1] : nd3;
                gx = sMean[(c + 1) * NDIG + dr] - rm.w;
            }
            if (c < 72)   // row < 8
                gy = sMean[(c + 9) * NDIG + ndn[k]] - rm.w;

            rbuf[k * 3 + 0] = rm.x;
            rbuf[k * 3 + 1] = rm.y;
            rbuf[k * 3 + 2] = rm.z;
            fbuf[k] = make_float4(rm.w, var, gx, gy);
        }

        // ---- stores: 4x STG.128 feats + 3x STG.128 resp (all 16B-aligned) ----
#pragma unroll
        for (int k = 0; k < 4; ++k)
            feats4[base + k] = fbuf[k];

        int rb = v * 3;
#pragma unroll
        for (int k = 0; k < 3; ++k)
            resp4[rb + k] = make_float4(rbuf[k * 4 + 0], rbuf[k * 4 + 1],
                                        rbuf[k * 4 + 2], rbuf[k * 4 + 3]);
    }
}

extern "C" void kernel_launch(void* const* d_in, const int* in_sizes, int n_in,
                              void* d_out, int out_size)
{
    const int*   grid = (const int*)d_in[0];     // sudoku_grid  [B,9,9] int32
    const float* ri   = (const float*)d_in[1];   // refractive_indices [9,9]
    const float* ab   = (const float*)d_in[2];   // absorption_coeffs  [9,9,3]
    const float* ts   = (const float*)d_in[3];   // thickness_scale    [1]

    // ncells from out_size: out = feats(4/cell) + resp(3/cell) = 7/cell.
    int total = out_size / 7;

    float* feats = (float*)d_out;
    float* resp  = (float*)d_out + (size_t)total * 4;

    build_lut_kernel<<<(NLUT + 255) / 256, 256>>>(ri, ab, ts);

    int ngroups = total >> 2;
    int nblocks = (ngroups + BLOCK - 1) / BLOCK;
    if (nblocks > GRID) nblocks = GRID;
    photonic_main_kernel<<<nblocks, BLOCK>>>(grid, feats, resp, total);
}

// round 14
// speedup vs baseline: 1.7372x; 1.7372x over previous
#include <cuda_runtime.h>

// SimplePhotonicRaytracer — GB300 sm_103a
//
// Evidence: R6 96us (DRAM 39%, L1TEX 68% top; 4-cells/thread strided stores);
// R7 106us (launch_bounds regression, reverted). R11: transpose design's only
// run crashed "misaligned address" — sResp (plain __shared__ float[]) landed
// at smem offset 16200 (8B boundary) and was read via LDS.128. Fixed with
// alignas(16) (deterministic compile-time property). R12/R13 never ran
// (acquisition timeouts). Resubmitting unchanged: the A/B vs R6 must stay
// attributable to the store-coalescing hypothesis alone.
//
// Hypothesis under test: R6 was store-wavefront-bound; make every output
// instruction minimum-wavefront (lane-contiguous STG.128 for feats; resp via
// conflict-free smem transpose: STS stride-3 words, gcd(3,32)=1; LDS.128
// readback covers all 32 banks per phase).
//
// Output layout: d_out = [ feats (B*81*4 f32) | resp (B*81*3 f32) ]  (validated R6)

#define GCELLS 81
#define NDIG   10
#define NLUT   (GCELLS * NDIG)
#define BLOCK  256
#define GRID   1184   // 148 SMs * 8 CTAs (smem 19.3KB/CTA -> 8 fit; no reg clamp)

__device__ float4 g_lut[NLUT];     // {r0, r1, r2, mean}

__global__ void build_lut_kernel(const float* __restrict__ ri,     // [81]
                                 const float* __restrict__ absorb, // [81*3]
                                 const float* __restrict__ tsp)    // [1]
{
    int e = blockIdx.x * blockDim.x + threadIdx.x;
    if (e >= NLUT) return;
    int c = e / NDIG;     // cell 0..80
    int d = e % NDIG;     // digit 0..9

    float n  = ri[c];
    float ts = *tsp;

    float height = 1e-4f + ts * (float)d;   // BASE_HEIGHT + scale*digit
    float path   = height * n;

    float rr = (1.0f - n) / (1.0f + n);     // Fresnel R = ((1-n)/(1+n))^2
    float tf = 1.0f - rr * rr;

    const float lam[3] = {6.5e-7f, 5.5e-7f, 4.5e-7f};
    float twopi_path = 6.283185307179586f * path;   // (2*pi*path)/lambda, ref order

    float r[3];
#pragma unroll
    for (int w = 0; w < 3; ++w) {
        float alpha  = fabsf(absorb[c * 3 + w]);
        float trans  = expf(-alpha * path);
        float interf = 0.5f * (1.0f + cosf(twopi_path / lam[w]));
        r[w] = tf * trans * interf;
    }

    float mean = (r[0] + r[1] + r[2]) * (1.0f / 3.0f);
    g_lut[e] = make_float4(r[0], r[1], r[2], mean);
}

__global__ void __launch_bounds__(BLOCK)
photonic_main_kernel(const int* __restrict__ grid,   // [B*81]
                     float* __restrict__ feats,      // [B*81*4]
                     float* __restrict__ resp,       // [B*81*3]
                     int total,                      // B*81 (multiple of 256 here)
                     int niter)                      // ceil(total / (gridDim*BLOCK))
{
    __shared__ float4 sLut[NLUT];        // {r0,r1,r2,mean}  (16B aligned)
    __shared__ float  sMean[NLUT];       // scalar mean for neighbor probes
    __shared__ alignas(16) float sResp[BLOCK * 3];  // transpose buffer — 16B
                                                    // alignment REQUIRED (LDS.128)

    for (int k = threadIdx.x; k < NLUT; k += BLOCK) {
        float4 v = g_lut[k];
        sLut[k]  = v;
        sMean[k] = v.w;
    }
    __syncthreads();

    float4* feats4 = reinterpret_cast<float4*>(feats);
    float4* resp4  = reinterpret_cast<float4*>(resp);
    const float4* sResp4 = reinterpret_cast<const float4*>(sResp);

    int tid = threadIdx.x;
    int ngroups_resp = (total >> 2) * 3;   // total*3/4 resp float4s

    for (int it = 0; it < niter; ++it) {
        int T0 = (blockIdx.x + it * gridDim.x) * BLOCK;  // block's first cell
        int t  = T0 + tid;                               // this thread's cell

        if (t < total) {
            int c = t % GCELLS;      // cell within board
            int j = c % 9;           // column

            int d = grid[t];         // coalesced LDG.32 (1 line/warp)
            float4 rm = sLut[c * NDIG + d];

            // unbiased var (ddof=1, W=3) — in registers, FMA pipe is idle
            float d0 = rm.x - rm.w, d1 = rm.y - rm.w, d2 = rm.z - rm.w;
            float var = (d0 * d0 + d1 * d1 + d2 * d2) * 0.5f;

            // gradients: diff with append(last) => 0 at j==8 / row==8;
            // neighbor loads stay inside the same board (guards j<8 / c<72)
            float gx = 0.0f, gy = 0.0f;
            if (j < 8) {
                int dr = grid[t + 1];
                gx = sMean[(c + 1) * NDIG + dr] - rm.w;
            }
            if (c < 72) {
                int dd = grid[t + 9];
                gy = sMean[(c + 9) * NDIG + dd] - rm.w;
            }

            // stage resp: stride-3 word STS (gcd(3,32)=1) -> conflict-free
            sResp[tid * 3 + 0] = rm.x;
            sResp[tid * 3 + 1] = rm.y;
            sResp[tid * 3 + 2] = rm.z;

            // feats: lane-contiguous STG.128 (each warp-instruction = 512B block)
            feats4[t] = make_float4(rm.w, var, gx, gy);
        }
        __syncthreads();

        // resp out: 768 floats = 192 float4s, lane-contiguous -> min wavefronts.
        if (tid < (BLOCK * 3) / 4) {
            int q = (T0 >> 2) * 3 + tid;    // exact: T0 is a multiple of 256
            if (q < ngroups_resp)
                resp4[q] = sResp4[tid];
        }
        __syncthreads();   // protect sResp before next iteration
    }
}

extern "C" void kernel_launch(void* const* d_in, const int* in_sizes, int n_in,
                              void* d_out, int out_size)
{
    const int*   grid = (const int*)d_in[0];     // sudoku_grid  [B,9,9] int32
    const float* ri   = (const float*)d_in[1];   // refractive_indices [9,9]
    const float* ab   = (const float*)d_in[2];   // absorption_coeffs  [9,9,3]
    const float* ts   = (const float*)d_in[3];   // thickness_scale    [1]

    int total = out_size / 7;                    // 7 output floats per cell

    float* feats = (float*)d_out;
    float* resp  = (float*)d_out + (size_t)total * 4;

    build_lut_kernel<<<(NLUT + 255) / 256, 256>>>(ri, ab, ts);

    long long span = (long long)GRID * BLOCK;
    int niter = (int)((total + span - 1) / span);
    photonic_main_kernel<<<GRID, BLOCK>>>(grid, feats, resp, total, niter);
}